// round 3
// baseline (speedup 1.0000x reference)
#include <cuda_runtime.h>
#include <math.h>

// ---------------------------------------------------------------------------
// Problem constants
//   B=4, T=8, H=8, D=128, dh=16, N=2048 (q/x0 nodes), M=8192 (edges)
//   Only the edge_attr branch matters (loop overwrites `out`).
// ---------------------------------------------------------------------------
constexpr int QROWS = 32 * 2048;   // 65536  global q rows (b*16384 + h*2048 + a)
constexpr int A_BLOCKS = 1024;     // 256 rows each (32 blocks per (b,h) slab)
constexpr int B_BLOCKS = 512;      // 128 rows each (16 per (b,h) slab)
constexpr int C_BLOCKS = 512;      // 128 rows each

// Scratch (static device globals — allocation-free per harness rules)
__device__ float g_oproc[(size_t)QROWS * 128];   // 32 MB, q-branch output (qf layout)
__device__ float g_kvpart[A_BLOCKS * 272];       // per-block partial kv(256)+ksum(16)
__device__ float g_kvred[32 * 272];              // reduced per-(b,h)

#define LN1E4_OVER_8 1.1512925464970231f

// ---------------------------------------------------------------------------
// Packed f32x2 helpers (sm_100+: ptxas never emits FFMA2 from C++)
// ---------------------------------------------------------------------------
__device__ __forceinline__ unsigned long long f32x2_pack(float lo, float hi) {
    unsigned long long r;
    asm("mov.b64 %0, {%1, %2};" : "=l"(r) : "f"(lo), "f"(hi));
    return r;
}
__device__ __forceinline__ void f32x2_fma(unsigned long long& d,
                                          unsigned long long a,
                                          unsigned long long b) {
    asm("fma.rn.f32x2 %0, %1, %2, %0;" : "+l"(d) : "l"(a), "l"(b));
}
__device__ __forceinline__ float2 f32x2_unpack(unsigned long long v) {
    float2 r;
    asm("mov.b64 {%0, %1}, %2;" : "=f"(r.x), "=f"(r.y) : "l"(v));
    return r;
}

// ---------------------------------------------------------------------------
// Kernel A: edge branch.
//   kr = Wk1@x+bk1, vr = Wv1@x+bv1, rope(k, time=m>>10), softmax per 16-chunk,
//   kv[d][e] += k*v, ksum[e] += k.
// smem (floats): Ws[128][256] | Xs[64][128] (=V after GEMM) | Kb[64][128]
//                | bias[256] | ropeC[64] | ropeS[64] | ksred[256]
// ---------------------------------------------------------------------------
__global__ __launch_bounds__(256, 1)
void kernelA(const float* __restrict__ X, const float* __restrict__ Wk,
             const float* __restrict__ bk, const float* __restrict__ Wv,
             const float* __restrict__ bv) {
    extern __shared__ float sm[];
    float* Ws    = sm;                   // 32768
    float* Xs    = sm + 32768;           // 8192 (also V buffer)
    float* Kb    = sm + 40960;           // 8192
    float* sbias = sm + 49152;           // 256
    float* ropeC = sm + 49408;           // 64
    float* ropeS = sm + 49472;           // 64
    float* ksred = sm + 49536;           // 256

    const int t  = threadIdx.x;
    const int tx = t & 31, ty = t >> 5;

    // Load weights transposed into smem: Ws[k][c], c<128 -> Wk, c>=128 -> Wv
    {
        const float* src = (t < 128) ? (Wk + t * 128) : (Wv + (t - 128) * 128);
#pragma unroll
        for (int q = 0; q < 32; q++) {
            float4 w = ((const float4*)src)[q];
            Ws[(4 * q + 0) * 256 + t] = w.x;
            Ws[(4 * q + 1) * 256 + t] = w.y;
            Ws[(4 * q + 2) * 256 + t] = w.z;
            Ws[(4 * q + 3) * 256 + t] = w.w;
        }
        sbias[t] = (t < 128) ? bk[t] : bv[t - 128];
    }
    if (t < 64) {
        int tm = t >> 3, i = t & 7;
        float freq = expf(-(float)i * LN1E4_OVER_8);
        float ang  = (float)tm * freq;
        ropeC[t] = cosf(ang);
        ropeS[t] = sinf(ang);
    }
    __syncthreads();

    // kv ownership: thread -> (d_own, e-pair) x uhalf replica
    const int d_own  = t >> 4;           // 0..15
    const int epair  = t & 7;            // e0 = 2*epair
    const int uhalf  = (t >> 3) & 1;     // which half of 512 units
    unsigned long long kv2 = 0ull;       // packed kv[d_own][2*epair .. +1]
    float ks_acc = 0.f;                  // ksum slice (old mapping: e = t&15)
    const int e_sum = t & 15, sl_sum = t >> 4;

    const int row_base = blockIdx.x * 256;   // global edge row
    const int m_base   = row_base & 8191;    // node index within slab

    const unsigned long long* W2 = (const unsigned long long*)Ws;

    for (int tile = 0; tile < 4; tile++) {
        const int r0 = row_base + tile * 64;

        // Coalesced load of 64x128 input tile
#pragma unroll
        for (int p = 0; p < 8; p++) {
            int idx = t + 256 * p;
            int rr = idx >> 5, qq = idx & 31;
            ((float4*)Xs)[rr * 32 + qq] =
                ((const float4*)(X + (size_t)(r0 + rr) * 128))[qq];
        }
        __syncthreads();

        // GEMM: 64 rows x 256 cols, K=128. Thread cols: {2tx, 2tx+1}+64*j2.
        unsigned long long acc2[8][4];
#pragma unroll
        for (int i = 0; i < 8; i++)
#pragma unroll
            for (int j = 0; j < 4; j++) acc2[i][j] = 0ull;

#pragma unroll 4
        for (int k4 = 0; k4 < 128; k4 += 4) {
            float4 xv[8];
#pragma unroll
            for (int ri = 0; ri < 8; ri++)
                xv[ri] = *(const float4*)(Xs + (ty * 8 + ri) * 128 + k4);
            unsigned long long wp[4][4];
#pragma unroll
            for (int kk = 0; kk < 4; kk++)
#pragma unroll
                for (int j2 = 0; j2 < 4; j2++)
                    wp[kk][j2] = W2[(k4 + kk) * 128 + tx + 32 * j2];
#pragma unroll
            for (int ri = 0; ri < 8; ri++) {
                float xs[4] = {xv[ri].x, xv[ri].y, xv[ri].z, xv[ri].w};
#pragma unroll
                for (int kk = 0; kk < 4; kk++) {
                    unsigned long long xx = f32x2_pack(xs[kk], xs[kk]);
#pragma unroll
                    for (int j2 = 0; j2 < 4; j2++)
                        f32x2_fma(acc2[ri][j2], xx, wp[kk][j2]);
                }
            }
        }
        __syncthreads();   // Xs reads done; safe to overwrite as V buffer

        // Store K (Kb) and V (Xs) with bias, packed float2 stores
#pragma unroll
        for (int ri = 0; ri < 8; ri++) {
            int rr = ty * 8 + ri;
#pragma unroll
            for (int j2 = 0; j2 < 4; j2++) {
                int c = 2 * tx + 64 * j2;
                float2 p = f32x2_unpack(acc2[ri][j2]);
                p.x += sbias[c];
                p.y += sbias[c + 1];
                if (j2 < 2)
                    *(float2*)(Kb + rr * 128 + c) = p;
                else
                    *(float2*)(Xs + rr * 128 + (c - 128)) = p;
            }
        }
        __syncthreads();

        // rope + softmax on K, per (row, subrow) unit
#pragma unroll
        for (int uu = 0; uu < 2; uu++) {
            int u  = t + 256 * uu;
            int rr = u >> 3, r = u & 7;
            int m  = m_base + tile * 64 + rr;
            int tmo = (m >> 10) << 3;          // rope table row
            float* kp = Kb + rr * 128 + r * 16;
            float kx[16];
#pragma unroll
            for (int q = 0; q < 4; q++) {
                float4 v = *(float4*)(kp + 4 * q);
                kx[4*q] = v.x; kx[4*q+1] = v.y; kx[4*q+2] = v.z; kx[4*q+3] = v.w;
            }
#pragma unroll
            for (int i = 0; i < 8; i++) {
                float c = ropeC[tmo + i], s = ropeS[tmo + i];
                float a0 = kx[2*i], a1 = kx[2*i+1];
                kx[2*i]   = a0 * c - a1 * s;
                kx[2*i+1] = a0 * s + a1 * c;
            }
            float mx = kx[0];
#pragma unroll
            for (int i = 1; i < 16; i++) mx = fmaxf(mx, kx[i]);
            float ssum = 0.f;
#pragma unroll
            for (int i = 0; i < 16; i++) { kx[i] = __expf(kx[i] - mx); ssum += kx[i]; }
            float inv = 1.0f / ssum;
#pragma unroll
            for (int i = 0; i < 16; i++) kx[i] *= inv;
#pragma unroll
            for (int q = 0; q < 4; q++)
                *(float4*)(kp + 4 * q) =
                    make_float4(kx[4*q], kx[4*q+1], kx[4*q+2], kx[4*q+3]);
        }
        __syncthreads();

        // kv accumulation: each thread covers 256 of 512 units for its
        // (d_own, e-pair); V loaded as 8-byte LDS, packed FMA.
        const unsigned long long* V2 = (const unsigned long long*)Xs;
#pragma unroll 8
        for (int uu = 0; uu < 256; uu++) {
            int u = uhalf * 256 + uu;
            int base = (u >> 3) * 128 + (u & 7) * 16;
            float kd = Kb[base + d_own];
            unsigned long long vv = V2[(base >> 1) + epair];
            f32x2_fma(kv2, f32x2_pack(kd, kd), vv);
        }
        // ksum: thread sums its 32-unit slice for dim e_sum
#pragma unroll 8
        for (int u2 = 0; u2 < 32; u2++) {
            int u = sl_sum * 32 + u2;
            int base = (u >> 3) * 128 + (u & 7) * 16;
            ks_acc += Kb[base + e_sum];
        }
        __syncthreads();
    }

    // merge uhalf replicas (lanes l and l+8 hold same (d, e-pair))
    unsigned long long other = __shfl_down_sync(0xffffffffu, kv2, 8);
    if (uhalf == 0) {
        float2 a = f32x2_unpack(kv2), b = f32x2_unpack(other);
        g_kvpart[blockIdx.x * 272 + d_own * 16 + 2 * epair]     = a.x + b.x;
        g_kvpart[blockIdx.x * 272 + d_own * 16 + 2 * epair + 1] = a.y + b.y;
    }
    ksred[t] = ks_acc;
    __syncthreads();
    if (t < 16) {
        float s = 0.f;
#pragma unroll
        for (int j = 0; j < 16; j++) s += ksred[j * 16 + t];
        g_kvpart[blockIdx.x * 272 + 256 + t] = s;
    }
}

// ---------------------------------------------------------------------------
// Reduce block partials -> per-(b,h) kv + ksum. 32 groups x 32 blocks each.
// ---------------------------------------------------------------------------
__global__ void kernelR() {
    int g = blockIdx.x, v = threadIdx.x;   // 272 threads
    float s = 0.f;
#pragma unroll 8
    for (int p = 0; p < 32; p++) s += g_kvpart[(g * 32 + p) * 272 + v];
    g_kvred[g * 272 + v] = s;
}

// ---------------------------------------------------------------------------
// Kernel B: q branch. qr = Wq@x+bq, softmax per 16-chunk, rope(time=a>>8),
//   Dinv = 1/max(q.ksum,1e-8), o = q + (q@kv)*Dinv  -> g_oproc (qf layout).
// 512 blocks x 128 rows, 2 blocks/SM.
// ---------------------------------------------------------------------------
__global__ __launch_bounds__(256, 2)
void kernelB(const float* __restrict__ Q, const float* __restrict__ Wq,
             const float* __restrict__ bq) {
    extern __shared__ float sm[];
    float* Ws    = sm;             // 16384
    float* Xs    = sm + 16384;     // 8192
    float* sbias = sm + 24576;     // 128
    float* ropeC = sm + 24704;     // 64
    float* ropeS = sm + 24768;     // 64
    float* skv   = sm + 24832;     // 272

    const int t = threadIdx.x;
    const int tx = t & 31, ty = t >> 5;

    if (t < 128) {
        const float* src = Wq + t * 128;
#pragma unroll
        for (int q = 0; q < 32; q++) {
            float4 w = ((const float4*)src)[q];
            Ws[(4*q+0)*128 + t] = w.x; Ws[(4*q+1)*128 + t] = w.y;
            Ws[(4*q+2)*128 + t] = w.z; Ws[(4*q+3)*128 + t] = w.w;
        }
        sbias[t] = bq[t];
    }
    {
        int g = blockIdx.x >> 4;   // 16 blocks per 2048-row (b,h) slab
        for (int i = t; i < 272; i += 256) skv[i] = g_kvred[g * 272 + i];
    }
    if (t < 64) {
        int tm = t >> 3, i = t & 7;
        float freq = expf(-(float)i * LN1E4_OVER_8);
        float ang  = (float)tm * freq;
        ropeC[t] = cosf(ang);
        ropeS[t] = sinf(ang);
    }
    __syncthreads();

    const int row_base = blockIdx.x * 128;
    const int a_base   = row_base & 2047;
    const unsigned long long* W2 = (const unsigned long long*)Ws;

    for (int tile = 0; tile < 2; tile++) {
        const int r0 = row_base + tile * 64;
#pragma unroll
        for (int p = 0; p < 8; p++) {
            int idx = t + 256 * p;
            int rr = idx >> 5, qq = idx & 31;
            ((float4*)Xs)[rr * 32 + qq] =
                ((const float4*)(Q + (size_t)(r0 + rr) * 128))[qq];
        }
        __syncthreads();

        unsigned long long acc2[8][2];
#pragma unroll
        for (int i = 0; i < 8; i++) { acc2[i][0] = 0ull; acc2[i][1] = 0ull; }

#pragma unroll 4
        for (int k4 = 0; k4 < 128; k4 += 4) {
            float4 xv[8];
#pragma unroll
            for (int ri = 0; ri < 8; ri++)
                xv[ri] = *(const float4*)(Xs + (ty * 8 + ri) * 128 + k4);
            unsigned long long wp[4][2];
#pragma unroll
            for (int kk = 0; kk < 4; kk++)
#pragma unroll
                for (int j2 = 0; j2 < 2; j2++)
                    wp[kk][j2] = W2[(k4 + kk) * 64 + tx + 32 * j2];
#pragma unroll
            for (int ri = 0; ri < 8; ri++) {
                float xs[4] = {xv[ri].x, xv[ri].y, xv[ri].z, xv[ri].w};
#pragma unroll
                for (int kk = 0; kk < 4; kk++) {
                    unsigned long long xx = f32x2_pack(xs[kk], xs[kk]);
                    f32x2_fma(acc2[ri][0], xx, wp[kk][0]);
                    f32x2_fma(acc2[ri][1], xx, wp[kk][1]);
                }
            }
        }
        __syncthreads();

        // store projected q (+bias) back into Xs
#pragma unroll
        for (int ri = 0; ri < 8; ri++) {
            int rr = ty * 8 + ri;
#pragma unroll
            for (int j2 = 0; j2 < 2; j2++) {
                int c = 2 * tx + 64 * j2;
                float2 p = f32x2_unpack(acc2[ri][j2]);
                p.x += sbias[c];
                p.y += sbias[c + 1];
                *(float2*)(Xs + rr * 128 + c) = p;
            }
        }
        __syncthreads();

        // epilogue per (row, subrow)
#pragma unroll
        for (int uu = 0; uu < 2; uu++) {
            int u  = t + 256 * uu;
            int rr = u >> 3, r = u & 7;
            int a  = a_base + tile * 64 + rr;
            int tmo = (a >> 8) << 3;
            float* qp = Xs + rr * 128 + r * 16;
            float qx[16];
#pragma unroll
            for (int q = 0; q < 4; q++) {
                float4 v = *(float4*)(qp + 4 * q);
                qx[4*q] = v.x; qx[4*q+1] = v.y; qx[4*q+2] = v.z; qx[4*q+3] = v.w;
            }
            // softmax FIRST (reference order for q)
            float mx = qx[0];
#pragma unroll
            for (int i = 1; i < 16; i++) mx = fmaxf(mx, qx[i]);
            float ssum = 0.f;
#pragma unroll
            for (int i = 0; i < 16; i++) { qx[i] = __expf(qx[i] - mx); ssum += qx[i]; }
            float inv = 1.0f / ssum;
#pragma unroll
            for (int i = 0; i < 16; i++) qx[i] *= inv;
            // then rope
#pragma unroll
            for (int i = 0; i < 8; i++) {
                float c = ropeC[tmo + i], s = ropeS[tmo + i];
                float a0 = qx[2*i], a1 = qx[2*i+1];
                qx[2*i]   = a0 * c - a1 * s;
                qx[2*i+1] = a0 * s + a1 * c;
            }
            // D_inv and o = q + (q@kv)*Dinv
            float dotv = 0.f;
#pragma unroll
            for (int e = 0; e < 16; e++) dotv += qx[e] * skv[256 + e];
            float Dinv = 1.0f / fmaxf(dotv, 1e-8f);
            float o[16];
#pragma unroll
            for (int e = 0; e < 16; e++) {
                float s = 0.f;
#pragma unroll
                for (int d = 0; d < 16; d++) s += qx[d] * skv[d * 16 + e];
                o[e] = qx[e] + s * Dinv;
            }
            float* op = g_oproc + (size_t)(r0 + rr) * 128 + r * 16;
#pragma unroll
            for (int q = 0; q < 4; q++)
                *(float4*)(op + 4 * q) =
                    make_float4(o[4*q], o[4*q+1], o[4*q+2], o[4*q+3]);
        }
        __syncthreads();
    }
}

// ---------------------------------------------------------------------------
// Kernel C: gather heads -> combined row, GEMM with Wo, +bo, write d_out.
//   combined[b][s][16h+e] = oproc[b*16384 + h*2048 + s/8][16*(s%8)+e]
// 512 blocks x 128 rows, 2 blocks/SM.
// ---------------------------------------------------------------------------
__global__ __launch_bounds__(256, 2)
void kernelC(const float* __restrict__ Wo, const float* __restrict__ bo,
             float* __restrict__ out) {
    extern __shared__ float sm[];
    float* Ws    = sm;             // 16384
    float* Xs    = sm + 16384;     // 8192
    float* sbias = sm + 24576;     // 128

    const int t = threadIdx.x;
    const int tx = t & 31, ty = t >> 5;

    if (t < 128) {
        const float* src = Wo + t * 128;
#pragma unroll
        for (int q = 0; q < 32; q++) {
            float4 w = ((const float4*)src)[q];
            Ws[(4*q+0)*128 + t] = w.x; Ws[(4*q+1)*128 + t] = w.y;
            Ws[(4*q+2)*128 + t] = w.z; Ws[(4*q+3)*128 + t] = w.w;
        }
        sbias[t] = bo[t];
    }
    __syncthreads();

    const int row_base = blockIdx.x * 128;   // global s-row
    const unsigned long long* W2 = (const unsigned long long*)Ws;

    for (int tile = 0; tile < 2; tile++) {
        const int r0 = row_base + tile * 64;
        const int b  = r0 >> 14;
        // gather combined tile
#pragma unroll
        for (int p = 0; p < 8; p++) {
            int idx = t + 256 * p;
            int rr = idx >> 5, qq = idx & 31;
            int gs = r0 + rr;
            int s  = gs & 16383;
            int a  = s >> 3, r = s & 7;
            int h  = qq >> 2, e0 = (qq & 3) * 4;
            const float4* src = (const float4*)(g_oproc +
                ((size_t)b * 16384 + h * 2048 + a) * 128 + r * 16 + e0);
            ((float4*)Xs)[rr * 32 + qq] = *src;
        }
        __syncthreads();

        unsigned long long acc2[8][2];
#pragma unroll
        for (int i = 0; i < 8; i++) { acc2[i][0] = 0ull; acc2[i][1] = 0ull; }

#pragma unroll 4
        for (int k4 = 0; k4 < 128; k4 += 4) {
            float4 xv[8];
#pragma unroll
            for (int ri = 0; ri < 8; ri++)
                xv[ri] = *(const float4*)(Xs + (ty * 8 + ri) * 128 + k4);
            unsigned long long wp[4][2];
#pragma unroll
            for (int kk = 0; kk < 4; kk++)
#pragma unroll
                for (int j2 = 0; j2 < 2; j2++)
                    wp[kk][j2] = W2[(k4 + kk) * 64 + tx + 32 * j2];
#pragma unroll
            for (int ri = 0; ri < 8; ri++) {
                float xs[4] = {xv[ri].x, xv[ri].y, xv[ri].z, xv[ri].w};
#pragma unroll
                for (int kk = 0; kk < 4; kk++) {
                    unsigned long long xx = f32x2_pack(xs[kk], xs[kk]);
                    f32x2_fma(acc2[ri][0], xx, wp[kk][0]);
                    f32x2_fma(acc2[ri][1], xx, wp[kk][1]);
                }
            }
        }
        __syncthreads();

#pragma unroll
        for (int ri = 0; ri < 8; ri++) {
            int gs = r0 + ty * 8 + ri;
#pragma unroll
            for (int j2 = 0; j2 < 2; j2++) {
                int c = 2 * tx + 64 * j2;
                float2 p = f32x2_unpack(acc2[ri][j2]);
                p.x += sbias[c];
                p.y += sbias[c + 1];
                *(float2*)(out + (size_t)gs * 128 + c) = p;
            }
        }
        __syncthreads();
    }
}

// ---------------------------------------------------------------------------
// Inputs (metadata order): 0 x_0, 1 edge_attr, 2 q_data, 3 Wq, 4 bq,
//   5 Wk0, 6 bk0, 7 Wv0, 8 bv0, 9 Wk1, 10 bk1, 11 Wv1, 12 bv1, 13 Wo, 14 bo
// x_0 / Wk0 / Wv0 branch is dead (loop overwrites `out`) -> skipped.
// ---------------------------------------------------------------------------
extern "C" void kernel_launch(void* const* d_in, const int* in_sizes, int n_in,
                              void* d_out, int out_size) {
    const float* edge = (const float*)d_in[1];
    const float* qdat = (const float*)d_in[2];
    const float* Wq   = (const float*)d_in[3];
    const float* bq   = (const float*)d_in[4];
    const float* Wk1  = (const float*)d_in[9];
    const float* bk1  = (const float*)d_in[10];
    const float* Wv1  = (const float*)d_in[11];
    const float* bv1  = (const float*)d_in[12];
    const float* Wo   = (const float*)d_in[13];
    const float* bo   = (const float*)d_in[14];
    float* out = (float*)d_out;

    const size_t smA = (size_t)(32768 + 8192 + 8192 + 256 + 64 + 64 + 256) * 4;
    const size_t smB = (size_t)(16384 + 8192 + 128 + 64 + 64 + 272) * 4;
    const size_t smC = (size_t)(16384 + 8192 + 128) * 4;

    cudaFuncSetAttribute(kernelA, cudaFuncAttributeMaxDynamicSharedMemorySize, (int)smA);
    cudaFuncSetAttribute(kernelB, cudaFuncAttributeMaxDynamicSharedMemorySize, (int)smB);
    cudaFuncSetAttribute(kernelC, cudaFuncAttributeMaxDynamicSharedMemorySize, (int)smC);

    kernelA<<<A_BLOCKS, 256, smA>>>(edge, Wk1, bk1, Wv1, bv1);
    kernelR<<<32, 272>>>();
    kernelB<<<B_BLOCKS, 256, smB>>>(qdat, Wq, bq);
    kernelC<<<C_BLOCKS, 256, smC>>>(Wo, bo, out);
}

// round 4
// speedup vs baseline: 1.0010x; 1.0010x over previous
#include <cuda_runtime.h>
#include <math.h>

// ---------------------------------------------------------------------------
// Problem constants
//   B=4, T=8, H=8, D=128, dh=16, N=2048 (q/x0 nodes), M=8192 (edges)
//   Only the edge_attr branch matters (loop overwrites `out`).
// ---------------------------------------------------------------------------
constexpr int QROWS = 32 * 2048;   // 65536  global q rows (b*16384 + h*2048 + a)
constexpr int A_BLOCKS = 1024;     // 256 rows each (32 blocks per (b,h) slab)
constexpr int B_BLOCKS = 512;      // 128 rows each (16 per (b,h) slab)
constexpr int C_BLOCKS = 512;      // 128 rows each

// Scratch (static device globals — allocation-free per harness rules)
__device__ float g_oproc[(size_t)QROWS * 128];   // 32 MB, q-branch output (qf layout)
__device__ float g_kvpart[A_BLOCKS * 272];       // per-block partial kv(256)+ksum(16)
__device__ float g_kvred[32 * 272];              // reduced per-(b,h)

#define LN1E4_OVER_8 1.1512925464970231f

// ---------------------------------------------------------------------------
// Packed f32x2 helpers (sm_100+: ptxas never emits FFMA2 from C++)
// ---------------------------------------------------------------------------
__device__ __forceinline__ unsigned long long f32x2_pack(float lo, float hi) {
    unsigned long long r;
    asm("mov.b64 %0, {%1, %2};" : "=l"(r) : "f"(lo), "f"(hi));
    return r;
}
__device__ __forceinline__ void f32x2_fma(unsigned long long& d,
                                          unsigned long long a,
                                          unsigned long long b) {
    asm("fma.rn.f32x2 %0, %1, %2, %0;" : "+l"(d) : "l"(a), "l"(b));
}
__device__ __forceinline__ float2 f32x2_unpack(unsigned long long v) {
    float2 r;
    asm("mov.b64 {%0, %1}, %2;" : "=f"(r.x), "=f"(r.y) : "l"(v));
    return r;
}

// ---------------------------------------------------------------------------
// Kernel A: edge branch.
//   kr = Wk1@x+bk1, vr = Wv1@x+bv1, rope(k, time=m>>10), softmax per 16-chunk,
//   kv[d][e] += k*v, ksum[e] += k.
// smem (floats): Ws[128][256] | Xs[64][128] (=V after GEMM) | Kb[64][128]
//                | bias[256] | ropeC[64] | ropeS[64] | ksred[256]
// ---------------------------------------------------------------------------
__global__ __launch_bounds__(256, 1)
void kernelA(const float* __restrict__ X, const float* __restrict__ Wk,
             const float* __restrict__ bk, const float* __restrict__ Wv,
             const float* __restrict__ bv) {
    extern __shared__ float sm[];
    float* Ws    = sm;                   // 32768
    float* Xs    = sm + 32768;           // 8192 (also V buffer)
    float* Kb    = sm + 40960;           // 8192
    float* sbias = sm + 49152;           // 256
    float* ropeC = sm + 49408;           // 64
    float* ropeS = sm + 49472;           // 64
    float* ksred = sm + 49536;           // 256

    const int t  = threadIdx.x;
    const int tx = t & 31, ty = t >> 5;

    // Load weights transposed into smem: Ws[k][c], c<128 -> Wk, c>=128 -> Wv
    {
        const float* src = (t < 128) ? (Wk + t * 128) : (Wv + (t - 128) * 128);
#pragma unroll
        for (int q = 0; q < 32; q++) {
            float4 w = ((const float4*)src)[q];
            Ws[(4 * q + 0) * 256 + t] = w.x;
            Ws[(4 * q + 1) * 256 + t] = w.y;
            Ws[(4 * q + 2) * 256 + t] = w.z;
            Ws[(4 * q + 3) * 256 + t] = w.w;
        }
        sbias[t] = (t < 128) ? bk[t] : bv[t - 128];
    }
    if (t < 64) {
        int tm = t >> 3, i = t & 7;
        float freq = expf(-(float)i * LN1E4_OVER_8);
        float ang  = (float)tm * freq;
        ropeC[t] = cosf(ang);
        ropeS[t] = sinf(ang);
    }
    __syncthreads();

    // kv ownership: thread -> (d_own, e-pair) x uhalf replica
    const int d_own  = t >> 4;           // 0..15
    const int epair  = t & 7;            // e0 = 2*epair
    const int uhalf  = (t >> 3) & 1;     // which half of 512 units
    unsigned long long kv2 = 0ull;       // packed kv[d_own][2*epair .. +1]
    float ks_acc = 0.f;                  // ksum slice (old mapping: e = t&15)
    const int e_sum = t & 15, sl_sum = t >> 4;

    const int row_base = blockIdx.x * 256;   // global edge row
    const int m_base   = row_base & 8191;    // node index within slab

    const unsigned long long* W2 = (const unsigned long long*)Ws;

    for (int tile = 0; tile < 4; tile++) {
        const int r0 = row_base + tile * 64;

        // Coalesced load of 64x128 input tile
#pragma unroll
        for (int p = 0; p < 8; p++) {
            int idx = t + 256 * p;
            int rr = idx >> 5, qq = idx & 31;
            ((float4*)Xs)[rr * 32 + qq] =
                ((const float4*)(X + (size_t)(r0 + rr) * 128))[qq];
        }
        __syncthreads();

        // GEMM: 64 rows x 256 cols, K=128. Thread cols: {2tx, 2tx+1}+64*j2.
        unsigned long long acc2[8][4];
#pragma unroll
        for (int i = 0; i < 8; i++)
#pragma unroll
            for (int j = 0; j < 4; j++) acc2[i][j] = 0ull;

#pragma unroll 4
        for (int k4 = 0; k4 < 128; k4 += 4) {
            float4 xv[8];
#pragma unroll
            for (int ri = 0; ri < 8; ri++)
                xv[ri] = *(const float4*)(Xs + (ty * 8 + ri) * 128 + k4);
            unsigned long long wp[4][4];
#pragma unroll
            for (int kk = 0; kk < 4; kk++)
#pragma unroll
                for (int j2 = 0; j2 < 4; j2++)
                    wp[kk][j2] = W2[(k4 + kk) * 128 + tx + 32 * j2];
#pragma unroll
            for (int ri = 0; ri < 8; ri++) {
                float xs[4] = {xv[ri].x, xv[ri].y, xv[ri].z, xv[ri].w};
#pragma unroll
                for (int kk = 0; kk < 4; kk++) {
                    unsigned long long xx = f32x2_pack(xs[kk], xs[kk]);
#pragma unroll
                    for (int j2 = 0; j2 < 4; j2++)
                        f32x2_fma(acc2[ri][j2], xx, wp[kk][j2]);
                }
            }
        }
        __syncthreads();   // Xs reads done; safe to overwrite as V buffer

        // Store K (Kb) and V (Xs) with bias, packed float2 stores
#pragma unroll
        for (int ri = 0; ri < 8; ri++) {
            int rr = ty * 8 + ri;
#pragma unroll
            for (int j2 = 0; j2 < 4; j2++) {
                int c = 2 * tx + 64 * j2;
                float2 p = f32x2_unpack(acc2[ri][j2]);
                p.x += sbias[c];
                p.y += sbias[c + 1];
                if (j2 < 2)
                    *(float2*)(Kb + rr * 128 + c) = p;
                else
                    *(float2*)(Xs + rr * 128 + (c - 128)) = p;
            }
        }
        __syncthreads();

        // rope + softmax on K, per (row, subrow) unit
#pragma unroll
        for (int uu = 0; uu < 2; uu++) {
            int u  = t + 256 * uu;
            int rr = u >> 3, r = u & 7;
            int m  = m_base + tile * 64 + rr;
            int tmo = (m >> 10) << 3;          // rope table row
            float* kp = Kb + rr * 128 + r * 16;
            float kx[16];
#pragma unroll
            for (int q = 0; q < 4; q++) {
                float4 v = *(float4*)(kp + 4 * q);
                kx[4*q] = v.x; kx[4*q+1] = v.y; kx[4*q+2] = v.z; kx[4*q+3] = v.w;
            }
#pragma unroll
            for (int i = 0; i < 8; i++) {
                float c = ropeC[tmo + i], s = ropeS[tmo + i];
                float a0 = kx[2*i], a1 = kx[2*i+1];
                kx[2*i]   = a0 * c - a1 * s;
                kx[2*i+1] = a0 * s + a1 * c;
            }
            float mx = kx[0];
#pragma unroll
            for (int i = 1; i < 16; i++) mx = fmaxf(mx, kx[i]);
            float ssum = 0.f;
#pragma unroll
            for (int i = 0; i < 16; i++) { kx[i] = __expf(kx[i] - mx); ssum += kx[i]; }
            float inv = 1.0f / ssum;
#pragma unroll
            for (int i = 0; i < 16; i++) kx[i] *= inv;
#pragma unroll
            for (int q = 0; q < 4; q++)
                *(float4*)(kp + 4 * q) =
                    make_float4(kx[4*q], kx[4*q+1], kx[4*q+2], kx[4*q+3]);
        }
        __syncthreads();

        // kv accumulation: each thread covers 256 of 512 units for its
        // (d_own, e-pair); V loaded as 8-byte LDS, packed FMA.
        const unsigned long long* V2 = (const unsigned long long*)Xs;
#pragma unroll 8
        for (int uu = 0; uu < 256; uu++) {
            int u = uhalf * 256 + uu;
            int base = (u >> 3) * 128 + (u & 7) * 16;
            float kd = Kb[base + d_own];
            unsigned long long vv = V2[(base >> 1) + epair];
            f32x2_fma(kv2, f32x2_pack(kd, kd), vv);
        }
        // ksum: thread sums its 32-unit slice for dim e_sum
#pragma unroll 8
        for (int u2 = 0; u2 < 32; u2++) {
            int u = sl_sum * 32 + u2;
            int base = (u >> 3) * 128 + (u & 7) * 16;
            ks_acc += Kb[base + e_sum];
        }
        __syncthreads();
    }

    // merge uhalf replicas (lanes l and l+8 hold same (d, e-pair))
    unsigned long long other = __shfl_down_sync(0xffffffffu, kv2, 8);
    if (uhalf == 0) {
        float2 a = f32x2_unpack(kv2), b = f32x2_unpack(other);
        g_kvpart[blockIdx.x * 272 + d_own * 16 + 2 * epair]     = a.x + b.x;
        g_kvpart[blockIdx.x * 272 + d_own * 16 + 2 * epair + 1] = a.y + b.y;
    }
    ksred[t] = ks_acc;
    __syncthreads();
    if (t < 16) {
        float s = 0.f;
#pragma unroll
        for (int j = 0; j < 16; j++) s += ksred[j * 16 + t];
        g_kvpart[blockIdx.x * 272 + 256 + t] = s;
    }
}

// ---------------------------------------------------------------------------
// Reduce block partials -> per-(b,h) kv + ksum. 32 groups x 32 blocks each.
// ---------------------------------------------------------------------------
__global__ void kernelR() {
    int g = blockIdx.x, v = threadIdx.x;   // 272 threads
    float s = 0.f;
#pragma unroll 8
    for (int p = 0; p < 32; p++) s += g_kvpart[(g * 32 + p) * 272 + v];
    g_kvred[g * 272 + v] = s;
}

// ---------------------------------------------------------------------------
// Kernel B: q branch. qr = Wq@x+bq, softmax per 16-chunk, rope(time=a>>8),
//   Dinv = 1/max(q.ksum,1e-8), o = q + (q@kv)*Dinv  -> g_oproc (qf layout).
// 512 blocks x 128 rows, 2 blocks/SM.
// ---------------------------------------------------------------------------
__global__ __launch_bounds__(256, 2)
void kernelB(const float* __restrict__ Q, const float* __restrict__ Wq,
             const float* __restrict__ bq) {
    extern __shared__ float sm[];
    float* Ws    = sm;             // 16384
    float* Xs    = sm + 16384;     // 8192
    float* sbias = sm + 24576;     // 128
    float* ropeC = sm + 24704;     // 64
    float* ropeS = sm + 24768;     // 64
    float* skv   = sm + 24832;     // 272

    const int t = threadIdx.x;
    const int tx = t & 31, ty = t >> 5;

    if (t < 128) {
        const float* src = Wq + t * 128;
#pragma unroll
        for (int q = 0; q < 32; q++) {
            float4 w = ((const float4*)src)[q];
            Ws[(4*q+0)*128 + t] = w.x; Ws[(4*q+1)*128 + t] = w.y;
            Ws[(4*q+2)*128 + t] = w.z; Ws[(4*q+3)*128 + t] = w.w;
        }
        sbias[t] = bq[t];
    }
    {
        int g = blockIdx.x >> 4;   // 16 blocks per 2048-row (b,h) slab
        for (int i = t; i < 272; i += 256) skv[i] = g_kvred[g * 272 + i];
    }
    if (t < 64) {
        int tm = t >> 3, i = t & 7;
        float freq = expf(-(float)i * LN1E4_OVER_8);
        float ang  = (float)tm * freq;
        ropeC[t] = cosf(ang);
        ropeS[t] = sinf(ang);
    }
    __syncthreads();

    const int row_base = blockIdx.x * 128;
    const int a_base   = row_base & 2047;
    const unsigned long long* W2 = (const unsigned long long*)Ws;

    for (int tile = 0; tile < 2; tile++) {
        const int r0 = row_base + tile * 64;
#pragma unroll
        for (int p = 0; p < 8; p++) {
            int idx = t + 256 * p;
            int rr = idx >> 5, qq = idx & 31;
            ((float4*)Xs)[rr * 32 + qq] =
                ((const float4*)(Q + (size_t)(r0 + rr) * 128))[qq];
        }
        __syncthreads();

        unsigned long long acc2[8][2];
#pragma unroll
        for (int i = 0; i < 8; i++) { acc2[i][0] = 0ull; acc2[i][1] = 0ull; }

#pragma unroll 4
        for (int k4 = 0; k4 < 128; k4 += 4) {
            float4 xv[8];
#pragma unroll
            for (int ri = 0; ri < 8; ri++)
                xv[ri] = *(const float4*)(Xs + (ty * 8 + ri) * 128 + k4);
            unsigned long long wp[4][2];
#pragma unroll
            for (int kk = 0; kk < 4; kk++)
#pragma unroll
                for (int j2 = 0; j2 < 2; j2++)
                    wp[kk][j2] = W2[(k4 + kk) * 64 + tx + 32 * j2];
#pragma unroll
            for (int ri = 0; ri < 8; ri++) {
                float xs[4] = {xv[ri].x, xv[ri].y, xv[ri].z, xv[ri].w};
#pragma unroll
                for (int kk = 0; kk < 4; kk++) {
                    unsigned long long xx = f32x2_pack(xs[kk], xs[kk]);
                    f32x2_fma(acc2[ri][0], xx, wp[kk][0]);
                    f32x2_fma(acc2[ri][1], xx, wp[kk][1]);
                }
            }
        }
        __syncthreads();

        // store projected q (+bias) back into Xs
#pragma unroll
        for (int ri = 0; ri < 8; ri++) {
            int rr = ty * 8 + ri;
#pragma unroll
            for (int j2 = 0; j2 < 2; j2++) {
                int c = 2 * tx + 64 * j2;
                float2 p = f32x2_unpack(acc2[ri][j2]);
                p.x += sbias[c];
                p.y += sbias[c + 1];
                *(float2*)(Xs + rr * 128 + c) = p;
            }
        }
        __syncthreads();

        // epilogue per (row, subrow)
#pragma unroll
        for (int uu = 0; uu < 2; uu++) {
            int u  = t + 256 * uu;
            int rr = u >> 3, r = u & 7;
            int a  = a_base + tile * 64 + rr;
            int tmo = (a >> 8) << 3;
            float* qp = Xs + rr * 128 + r * 16;
            float qx[16];
#pragma unroll
            for (int q = 0; q < 4; q++) {
                float4 v = *(float4*)(qp + 4 * q);
                qx[4*q] = v.x; qx[4*q+1] = v.y; qx[4*q+2] = v.z; qx[4*q+3] = v.w;
            }
            // softmax FIRST (reference order for q)
            float mx = qx[0];
#pragma unroll
            for (int i = 1; i < 16; i++) mx = fmaxf(mx, qx[i]);
            float ssum = 0.f;
#pragma unroll
            for (int i = 0; i < 16; i++) { qx[i] = __expf(qx[i] - mx); ssum += qx[i]; }
            float inv = 1.0f / ssum;
#pragma unroll
            for (int i = 0; i < 16; i++) qx[i] *= inv;
            // then rope
#pragma unroll
            for (int i = 0; i < 8; i++) {
                float c = ropeC[tmo + i], s = ropeS[tmo + i];
                float a0 = qx[2*i], a1 = qx[2*i+1];
                qx[2*i]   = a0 * c - a1 * s;
                qx[2*i+1] = a0 * s + a1 * c;
            }
            // D_inv and o = q + (q@kv)*Dinv
            float dotv = 0.f;
#pragma unroll
            for (int e = 0; e < 16; e++) dotv += qx[e] * skv[256 + e];
            float Dinv = 1.0f / fmaxf(dotv, 1e-8f);
            float o[16];
#pragma unroll
            for (int e = 0; e < 16; e++) {
                float s = 0.f;
#pragma unroll
                for (int d = 0; d < 16; d++) s += qx[d] * skv[d * 16 + e];
                o[e] = qx[e] + s * Dinv;
            }
            float* op = g_oproc + (size_t)(r0 + rr) * 128 + r * 16;
#pragma unroll
            for (int q = 0; q < 4; q++)
                *(float4*)(op + 4 * q) =
                    make_float4(o[4*q], o[4*q+1], o[4*q+2], o[4*q+3]);
        }
        __syncthreads();
    }
}

// ---------------------------------------------------------------------------
// Kernel C: gather heads -> combined row, GEMM with Wo, +bo, write d_out.
//   combined[b][s][16h+e] = oproc[b*16384 + h*2048 + s/8][16*(s%8)+e]
// 512 blocks x 128 rows, 2 blocks/SM.
// ---------------------------------------------------------------------------
__global__ __launch_bounds__(256, 2)
void kernelC(const float* __restrict__ Wo, const float* __restrict__ bo,
             float* __restrict__ out) {
    extern __shared__ float sm[];
    float* Ws    = sm;             // 16384
    float* Xs    = sm + 16384;     // 8192
    float* sbias = sm + 24576;     // 128

    const int t = threadIdx.x;
    const int tx = t & 31, ty = t >> 5;

    if (t < 128) {
        const float* src = Wo + t * 128;
#pragma unroll
        for (int q = 0; q < 32; q++) {
            float4 w = ((const float4*)src)[q];
            Ws[(4*q+0)*128 + t] = w.x; Ws[(4*q+1)*128 + t] = w.y;
            Ws[(4*q+2)*128 + t] = w.z; Ws[(4*q+3)*128 + t] = w.w;
        }
        sbias[t] = bo[t];
    }
    __syncthreads();

    const int row_base = blockIdx.x * 128;   // global s-row
    const unsigned long long* W2 = (const unsigned long long*)Ws;

    for (int tile = 0; tile < 2; tile++) {
        const int r0 = row_base + tile * 64;
        const int b  = r0 >> 14;
        // gather combined tile
#pragma unroll
        for (int p = 0; p < 8; p++) {
            int idx = t + 256 * p;
            int rr = idx >> 5, qq = idx & 31;
            int gs = r0 + rr;
            int s  = gs & 16383;
            int a  = s >> 3, r = s & 7;
            int h  = qq >> 2, e0 = (qq & 3) * 4;
            const float4* src = (const float4*)(g_oproc +
                ((size_t)b * 16384 + h * 2048 + a) * 128 + r * 16 + e0);
            ((float4*)Xs)[rr * 32 + qq] = *src;
        }
        __syncthreads();

        unsigned long long acc2[8][2];
#pragma unroll
        for (int i = 0; i < 8; i++) { acc2[i][0] = 0ull; acc2[i][1] = 0ull; }

#pragma unroll 4
        for (int k4 = 0; k4 < 128; k4 += 4) {
            float4 xv[8];
#pragma unroll
            for (int ri = 0; ri < 8; ri++)
                xv[ri] = *(const float4*)(Xs + (ty * 8 + ri) * 128 + k4);
            unsigned long long wp[4][2];
#pragma unroll
            for (int kk = 0; kk < 4; kk++)
#pragma unroll
                for (int j2 = 0; j2 < 2; j2++)
                    wp[kk][j2] = W2[(k4 + kk) * 64 + tx + 32 * j2];
#pragma unroll
            for (int ri = 0; ri < 8; ri++) {
                float xs[4] = {xv[ri].x, xv[ri].y, xv[ri].z, xv[ri].w};
#pragma unroll
                for (int kk = 0; kk < 4; kk++) {
                    unsigned long long xx = f32x2_pack(xs[kk], xs[kk]);
                    f32x2_fma(acc2[ri][0], xx, wp[kk][0]);
                    f32x2_fma(acc2[ri][1], xx, wp[kk][1]);
                }
            }
        }
        __syncthreads();

#pragma unroll
        for (int ri = 0; ri < 8; ri++) {
            int gs = r0 + ty * 8 + ri;
#pragma unroll
            for (int j2 = 0; j2 < 2; j2++) {
                int c = 2 * tx + 64 * j2;
                float2 p = f32x2_unpack(acc2[ri][j2]);
                p.x += sbias[c];
                p.y += sbias[c + 1];
                *(float2*)(out + (size_t)gs * 128 + c) = p;
            }
        }
        __syncthreads();
    }
}

// ---------------------------------------------------------------------------
// Inputs (metadata order): 0 x_0, 1 edge_attr, 2 q_data, 3 Wq, 4 bq,
//   5 Wk0, 6 bk0, 7 Wv0, 8 bv0, 9 Wk1, 10 bk1, 11 Wv1, 12 bv1, 13 Wo, 14 bo
// x_0 / Wk0 / Wv0 branch is dead (loop overwrites `out`) -> skipped.
// ---------------------------------------------------------------------------
extern "C" void kernel_launch(void* const* d_in, const int* in_sizes, int n_in,
                              void* d_out, int out_size) {
    const float* edge = (const float*)d_in[1];
    const float* qdat = (const float*)d_in[2];
    const float* Wq   = (const float*)d_in[3];
    const float* bq   = (const float*)d_in[4];
    const float* Wk1  = (const float*)d_in[9];
    const float* bk1  = (const float*)d_in[10];
    const float* Wv1  = (const float*)d_in[11];
    const float* bv1  = (const float*)d_in[12];
    const float* Wo   = (const float*)d_in[13];
    const float* bo   = (const float*)d_in[14];
    float* out = (float*)d_out;

    const size_t smA = (size_t)(32768 + 8192 + 8192 + 256 + 64 + 64 + 256) * 4;
    const size_t smB = (size_t)(16384 + 8192 + 128 + 64 + 64 + 272) * 4;
    const size_t smC = (size_t)(16384 + 8192 + 128) * 4;

    cudaFuncSetAttribute(kernelA, cudaFuncAttributeMaxDynamicSharedMemorySize, (int)smA);
    cudaFuncSetAttribute(kernelB, cudaFuncAttributeMaxDynamicSharedMemorySize, (int)smB);
    cudaFuncSetAttribute(kernelC, cudaFuncAttributeMaxDynamicSharedMemorySize, (int)smC);

    kernelA<<<A_BLOCKS, 256, smA>>>(edge, Wk1, bk1, Wv1, bv1);
    kernelR<<<32, 272>>>();
    kernelB<<<B_BLOCKS, 256, smB>>>(qdat, Wq, bq);
    kernelC<<<C_BLOCKS, 256, smC>>>(Wo, bo, out);
}